// round 7
// baseline (speedup 1.0000x reference)
#include <cuda_runtime.h>
#include <math.h>

#define NCH   31
#define NREG  9
#define RPB   16
#define TPB   512
#define NBAND 2418            // 78 band groups * 31 channels
#define NSTRM 1550            // 50 stream groups * 31 channels
#define NTILES (NBAND + NSTRM)
#define PGRID 444             // persistent blocks (3 per SM on 148 SMs)
#define SCRATCH_N (1 + NREG * NCH * 7)

// scratch[0] = global target sum; per (r,c): {St1, St3, Sxt3, Syt3, Sp3, Sxp3, Syp3}
__device__ double g_scratch[SCRATCH_N];
__device__ unsigned int g_cnt = 0;

__device__ __forceinline__ float wsumf(float v) {
#pragma unroll
    for (int o = 16; o; o >>= 1) v += __shfl_down_sync(0xffffffffu, v, o);
    return v;
}
__device__ __forceinline__ double wsumd(double v) {
#pragma unroll
    for (int o = 16; o; o >>= 1) v += __shfl_down_sync(0xffffffffu, v, o);
    return v;
}

__global__ __launch_bounds__(TPB, 3) void coml_kernel(
    const float* __restrict__ pred, const float* __restrict__ targ,
    float* __restrict__ out) {
    const int tid  = threadIdx.x;
    const int lane = tid & 31, wid = tid >> 5;

    // thread col-band (float4 index == tid; all edges multiples of 4)
    int cb = -1, bxs = 0;
    if      (tid >= 50  && tid < 150) { cb = 0; bxs = 50;  }
    else if (tid >= 250 && tid < 350) { cb = 1; bxs = 250; }
    else if (tid >= 375 && tid < 475) { cb = 2; bxs = 375; }
    const float offb = (float)((tid - bxs) * 4);

    float gsum = 0.f;             // carried across ALL tiles this CTA handles
    __shared__ float sh[7 * 512];

    // static round-robin tile assignment: no atomics, no fetch barriers
    for (int t = blockIdx.x; t < NTILES; t += PGRID) {
        if (t < NBAND) {
            // ---------- band tile ----------
            const int ch = t / 78, i = t % 78;
            int rbm, g, bs;
            if      (i < 26) { rbm = 0; g = 12 + i; bs = 200;  }
            else if (i < 52) { rbm = 1; g = 36 + i; bs = 1000; }
            else             { rbm = 2; g = 41 + i; bs = 1500; }
            const int y0  = g * RPB;
            const int rlo = max(0, bs - y0);
            const int rhi = min(RPB, bs + 400 - y0);

            const size_t base4 = (((size_t)ch << 22) + ((size_t)y0 << 11)) >> 2;
            const float4* tp = (const float4*)targ + base4 + tid;
            const float4* pp = (const float4*)pred + base4 + tid;

            float SA[7];
#pragma unroll
            for (int k = 0; k < 7; k++) SA[k] = 0.f;

            for (int rr = 0; rr < rlo; rr++) {
                const float4 a = __ldcv(&tp[rr * 512]);
                gsum += (a.x + a.y) + (a.z + a.w);
            }
#pragma unroll 4
            for (int rr = rlo; rr < rhi; rr++) {
                const float4 v = __ldcv(&tp[rr * 512]);
                const float s1 = (v.x + v.y) + (v.z + v.w);
                gsum += s1;
                if (cb >= 0) {
                    const float i0f = (float)(y0 + rr - bs);
                    SA[0] += s1;
                    const float a3 = v.x*v.x*v.x, b3 = v.y*v.y*v.y;
                    const float c3 = v.z*v.z*v.z, d3 = v.w*v.w*v.w;
                    const float s3 = (a3 + b3) + (c3 + d3);
                    SA[1] += s3;
                    SA[2] = fmaf(i0f, s3, SA[2]);
                    SA[3] += fmaf(offb, s3, b3 + 2.f*c3 + 3.f*d3);
                    const float4 p = __ldcv(&pp[rr * 512]);
                    const float e3 = p.x*p.x*p.x, f3 = p.y*p.y*p.y;
                    const float g3 = p.z*p.z*p.z, h3 = p.w*p.w*p.w;
                    const float sp = (e3 + f3) + (g3 + h3);
                    SA[4] += sp;
                    SA[5] = fmaf(i0f, sp, SA[5]);
                    SA[6] += fmaf(offb, sp, f3 + 2.f*g3 + 3.f*h3);
                }
            }
            for (int rr = rhi; rr < RPB; rr++) {
                const float4 a = __ldcv(&tp[rr * 512]);
                gsum += (a.x + a.y) + (a.z + a.w);
            }

            // ---- band epilogue: 7 stats, 21 contiguous range sums ----
            __syncthreads();   // protect sh from previous band tile's readers
#pragma unroll
            for (int k = 0; k < 7; k++) sh[k * 512 + tid] = SA[k];
            __syncthreads();
            for (int item = wid; item < 21; item += 16) {
                const int b  = item / 7, st = item % 7;
                const int lo = (b == 0) ? 50 : (b == 1) ? 250 : 375;
                float s = 0.f;
                for (int idx = lo + lane; idx < lo + 100; idx += 32)
                    s += sh[st * 512 + idx];
                s = wsumf(s);
                if (lane == 0) {
                    const int r = rbm * 3 + b;
                    atomicAdd(&g_scratch[1 + (r * NCH + ch) * 7 + st], (double)s);
                }
            }
        } else {
            // ---------- stream tile: gsum only, no barriers, batched loads ----------
            const int s2 = t - NBAND;
            const int ch = s2 / 50, i = s2 % 50;
            int g;
            if      (i < 12) g = i;
            else if (i < 36) g = 26 + i;
            else if (i < 41) g = 52 + i;
            else             g = 78 + i;
            const size_t base4 = (((size_t)ch << 22) + ((size_t)(g * RPB) << 11)) >> 2;
            const float4* tp = (const float4*)targ + base4 + tid;
            float g0 = 0.f, g1 = 0.f, g2 = 0.f, g3 = 0.f;
#pragma unroll
            for (int rr = 0; rr < RPB; rr += 4) {
                const float4 a = __ldcv(&tp[(rr + 0) * 512]);
                const float4 b = __ldcv(&tp[(rr + 1) * 512]);
                const float4 c = __ldcv(&tp[(rr + 2) * 512]);
                const float4 d = __ldcv(&tp[(rr + 3) * 512]);
                g0 += (a.x + a.y) + (a.z + a.w);
                g1 += (b.x + b.y) + (b.z + b.w);
                g2 += (c.x + c.y) + (c.z + c.w);
                g3 += (d.x + d.y) + (d.z + d.w);
            }
            gsum += (g0 + g1) + (g2 + g3);
        }
    }

    // ---- one gsum flush per CTA ----
    {
        float v = wsumf(gsum);
        __shared__ float wg[16];
        __syncthreads();       // sh/wg reuse safety
        if (lane == 0) wg[wid] = v;
        __syncthreads();
        if (tid == 0) {
            float s = 0.f;
#pragma unroll
            for (int w = 0; w < 16; w++) s += wg[w];
            atomicAdd(&g_scratch[0], (double)s);
        }
    }

    // ---- last CTA computes the loss and resets state ----
    __threadfence();
    __shared__ unsigned int ticket;
    if (tid == 0) ticket = atomicAdd(&g_cnt, 1u);
    __syncthreads();
    if (ticket == PGRID - 1) {
        __threadfence();
        volatile double* vs = g_scratch;
        const double mean_t = vs[0] / ((double)NCH * 2048.0 * 2048.0);
        double term = 0.0;
        if (tid < NREG * NCH) {
            const int r = tid / NCH;
            const double St1  = vs[1 + tid*7 + 0], St3  = vs[1 + tid*7 + 1];
            const double Sxt3 = vs[1 + tid*7 + 2], Syt3 = vs[1 + tid*7 + 3];
            const double Sp3  = vs[1 + tid*7 + 4], Sxp3 = vs[1 + tid*7 + 5];
            const double Syp3 = vs[1 + tid*7 + 6];
            const double cxt = (St3 != 0.0) ? Sxt3 / St3 : 0.0;
            const double cyt = (St3 != 0.0) ? Syt3 / St3 : 0.0;
            const double cxp = (Sp3 != 0.0) ? Sxp3 / Sp3 : 0.0;
            const double cyp = (Sp3 != 0.0) ? Syp3 / Sp3 : 0.0;
            const double dx = cxp - cxt, dy = cyp - cyt;
            term = sqrt(dx * dx + dy * dy) * ((St1 / 160000.0) / mean_t);
            if (r == 4) term *= 5.0;  // fundamental region weight
        }
        term = wsumd(term);
        __shared__ double wpart[16];
        if (lane == 0) wpart[wid] = term;
        __syncthreads();
        if (tid == 0) {
            double s = 0.0;
#pragma unroll
            for (int w = 0; w < 16; w++) s += wpart[w];
            out[0] = (float)(s / (double)(NREG * NCH));
            g_cnt = 0;
        }
        for (int i = tid; i < SCRATCH_N; i += TPB) g_scratch[i] = 0.0;
    }
}

extern "C" void kernel_launch(void* const* d_in, const int* in_sizes, int n_in,
                              void* d_out, int out_size) {
    const float* pred = (const float*)d_in[0];
    const float* targ = (const float*)d_in[1];
    coml_kernel<<<PGRID, TPB>>>(pred, targ, (float*)d_out);
}